// round 9
// baseline (speedup 1.0000x reference)
#include <cuda_runtime.h>
#include <cuda_fp16.h>
#include <cstdint>

#define BTn 32768
#define Tn  256
#define Cn  384
#define Hn  6
#define Vn  65
#define Fn  1536

// ---------------- scratch (device globals; allocation-free rule) -----------
__device__ __half g_x[BTn*Cn];                      // embeddings fp16
__device__ __half g_bqkvh[128*Cn], g_bqkvl[128*Cn]; // qkv W split [Npad=128,K=384]
__device__ float  g_qkv[BTn*72];                    // qkv activations (f32)
__device__ __half g_att[BTn*32];                    // attn out fp16, Kpad=32
__device__ __half g_bprojh[Cn*32], g_bprojl[Cn*32]; // proj W split [384,Kpad=32]
__device__ __half g_x2[BTn*Cn];                     // proj out fp16
__device__ __half g_b1h[Fn*Cn], g_b1l[Fn*Cn];       // W1^T split [1536,384]
__device__ __half g_h[BTn*Fn];                      // ffn hidden fp16
__device__ __half g_b2h[Cn*Fn], g_b2l[Cn*Fn];       // W2^T split [384,1536]
__device__ __half g_x3[BTn*Cn];                     // ffn out fp16
__device__ __half g_blmh[128*Cn], g_blml[128*Cn];   // Wlm^T split [Npad=128,384]
__device__ float  g_rowloss[BTn];

// ---------------- helpers ----------------------------------------------
__device__ __forceinline__ uint32_t smem_u32(const void* p) {
    return (uint32_t)__cvta_generic_to_shared(p);
}

__device__ __forceinline__ void cp16(uint32_t dst, const void* src) {
    asm volatile("cp.async.cg.shared.global [%0], [%1], 16;" :: "r"(dst), "l"(src));
}
#define CP_COMMIT() asm volatile("cp.async.commit_group;" ::: "memory")
#define CP_WAIT(n)  asm volatile("cp.async.wait_group %0;" :: "n"(n) : "memory")

__device__ __forceinline__ void mma_f16(float* d, const uint32_t* a, uint32_t b0, uint32_t b1) {
    asm volatile(
        "mma.sync.aligned.m16n8k16.row.col.f32.f16.f16.f32 "
        "{%0,%1,%2,%3}, {%4,%5,%6,%7}, {%8,%9}, {%0,%1,%2,%3};"
        : "+f"(d[0]), "+f"(d[1]), "+f"(d[2]), "+f"(d[3])
        : "r"(a[0]), "r"(a[1]), "r"(a[2]), "r"(a[3]), "r"(b0), "r"(b1));
}

__device__ __forceinline__ void ldm_x4(uint32_t* r, uint32_t addr) {
    asm volatile("ldmatrix.sync.aligned.m8n8.x4.shared.b16 {%0,%1,%2,%3}, [%4];"
        : "=r"(r[0]), "=r"(r[1]), "=r"(r[2]), "=r"(r[3]) : "r"(addr));
}

__device__ __forceinline__ void split2h(float v, __half& h, __half& l) {
    h = __float2half_rn(v);
    l = __float2half_rn(v - __half2float(h));
}

// ---------------- fused pack + embed (one launch) ---------------------------
#define S0 (128*Cn)
#define S1 (Cn*32)
#define S2 (Fn*Cn)
#define S3 (Cn*Fn)
#define S4 (128*Cn)
#define PACKT (S0 + S1 + S2 + S3 + S4)

__global__ void pack_embed(const float* __restrict__ Wq, const float* __restrict__ Wk,
                           const float* __restrict__ Wv, const float* __restrict__ Wproj,
                           const float* __restrict__ W1, const float* __restrict__ W2,
                           const float* __restrict__ Wlm,
                           const int* __restrict__ idx, const float* __restrict__ tok,
                           const float* __restrict__ pos) {
    int i = blockIdx.x * blockDim.x + threadIdx.x;
    if (i < PACKT) {
        float v; __half *hi, *lo; int o;
        if (i < S0) {
            o = i; int n = o / Cn, k = o - n * Cn;
            if (n < 72) {
                int g = n / 24, rem = n - g * 24, h = rem >> 2, d = rem & 3;
                const float* W = (g == 0) ? Wq : (g == 1) ? Wk : Wv;
                v = W[(h * Cn + k) * 4 + d];
            } else v = 0.f;
            hi = g_bqkvh; lo = g_bqkvl;
        } else if (i < S0 + S1) {
            o = i - S0; int n = o >> 5, k = o & 31;
            v = (k < 24) ? Wproj[k * Cn + n] : 0.f;
            hi = g_bprojh; lo = g_bprojl;
        } else if (i < S0 + S1 + S2) {
            o = i - S0 - S1; int n = o / Cn, k = o - n * Cn;
            v = W1[(size_t)k * Fn + n];
            hi = g_b1h; lo = g_b1l;
        } else if (i < S0 + S1 + S2 + S3) {
            o = i - S0 - S1 - S2; int n = o / Fn, k = o - n * Fn;
            v = W2[(size_t)k * Cn + n];
            hi = g_b2h; lo = g_b2l;
        } else {
            o = i - S0 - S1 - S2 - S3; int n = o / Cn, k = o - n * Cn;
            v = (n < Vn) ? Wlm[k * Vn + n] : 0.f;
            hi = g_blmh; lo = g_blml;
        }
        __half h, l; split2h(v, h, l);
        hi[o] = h; lo[o] = l;
        return;
    }
    int e = i - PACKT;
    if (e >= BTn * Cn) return;
    int bt = e / Cn, c = e - bt * Cn;
    int t = bt & (Tn - 1);
    g_x[e] = __float2half_rn(tok[__ldg(&idx[bt]) * Cn + c] + pos[t * Cn + c]);
}

// ---------------- fp16 2-product GEMM, 64x64 warp tiles ---------------------
// C[M,N] = A[M,K] @ (Bh+Bl)^T. 128x128 CTA tile, BK=32, 4 warps (2M x 2N),
// warp tile 64x64: each smem slice read by only 2 warps (48KB reads/chunk
// vs 80KB with the old 4x2/32x64 arrangement). 24 ldm : 128 HMMA per chunk.
#define TILE_B 8192
#define STAGE_B (3 * TILE_B)     // A, Bh, Bl = 24576
#define NSTAGE 4

template <bool RELU, bool HASBIAS, bool HALFOUT>
__global__ __launch_bounds__(128, 2) void tc_gemm(
    const __half* __restrict__ A, int Kpad,
    const __half* __restrict__ Bh, const __half* __restrict__ Bl,
    const float* __restrict__ bias,
    float* __restrict__ Cf, int ldc, int Nreal,
    __half* __restrict__ Ch, int Npad)
{
    extern __shared__ char smem[];
    const int tid  = threadIdx.x;
    const int lane = tid & 31, wid = tid >> 5;   // 4 warps
    const int wm = wid & 1, wn = wid >> 1;       // 2x2 warp grid, 64x64 tiles
    const int m0 = blockIdx.y * 128, n0 = blockIdx.x * 128;

    const __half* gsrc[3] = {
        A  + (size_t)m0 * Kpad,
        Bh + (size_t)n0 * Kpad,
        Bl + (size_t)n0 * Kpad };

    const int nk = Kpad / 32;
    const uint32_t sbase = smem_u32(smem);

    auto load_stage = [&](int stage, int c) {
        uint32_t dst0 = sbase + stage * STAGE_B;
        int kc0 = c * 32;
#pragma unroll
        for (int tile = 0; tile < 3; tile++) {
            const __half* g = gsrc[tile] + kc0;
#pragma unroll
            for (int t = 0; t < 4; t++) {
                int j = tid + t * 128;               // 0..511
                int row = j >> 2, x = j & 3;
                uint32_t sw = (uint32_t)(row * 64 + ((x ^ ((row >> 1) & 3)) << 4));
                cp16(dst0 + tile * TILE_B + sw, g + (size_t)row * Kpad + x * 8);
            }
        }
        CP_COMMIT();
    };

    float acc[4][8][4];
#pragma unroll
    for (int mi = 0; mi < 4; mi++)
#pragma unroll
        for (int nj = 0; nj < 8; nj++)
#pragma unroll
            for (int q = 0; q < 4; q++) acc[mi][nj][q] = 0.f;

    load_stage(0, 0);
    if (nk > 1) load_stage(1, 1);
    if (nk > 2) load_stage(2, 2);

    // ldmatrix lane addressing with swizzle (row stride 64B, 4x 16B chunks)
    const int r = lane & 15, xh = lane >> 4, sxor = (r >> 1) & 3;
    const uint32_t offK0 = (uint32_t)(r * 64 + ((xh ^ sxor) << 4));
    const uint32_t offK1 = (uint32_t)(r * 64 + (((xh | 2) ^ sxor) << 4));
    const int r8 = lane >> 2, q4 = lane & 3;

    for (int c = 0; c < nk; c++) {
        if (c + 3 <= nk) { CP_WAIT(2); }
        else if (c + 2 == nk) { CP_WAIT(1); }
        else { CP_WAIT(0); }
        __syncthreads();
        if (c + 3 < nk) load_stage((c + 3) % NSTAGE, c + 3);

        const uint32_t st = sbase + (uint32_t)((c % NSTAGE) * STAGE_B);
        const uint32_t stA  = st;
        const uint32_t stBh = st + TILE_B;
        const uint32_t stBl = st + 2 * TILE_B;

#pragma unroll
        for (int step = 0; step < 2; step++) {
            const uint32_t offK = step ? offK1 : offK0;
            // A fragments: 4 x m16 covering 64 rows
            uint32_t a[4][4];
            const uint32_t abase = (uint32_t)(wm * 4096) + offK;
            ldm_x4(a[0], stA + abase);
            ldm_x4(a[1], stA + abase + 1024);
            ldm_x4(a[2], stA + abase + 2048);
            ldm_x4(a[3], stA + abase + 3072);
            const uint32_t bbase = (uint32_t)(wn * 4096) + offK;
            uint32_t b[2][4];

            // ---- h pass: 32 independent HMMAs, B n16-frags double-buffered
            ldm_x4(b[0], stBh + bbase);
#pragma unroll
            for (int p = 0; p < 4; p++) {
                const int cur = p & 1;
                if (p < 3) ldm_x4(b[cur ^ 1], stBh + bbase + (uint32_t)((p + 1) * 1024));
#pragma unroll
                for (int mi = 0; mi < 4; mi++) {
                    mma_f16(acc[mi][2*p],   a[mi], b[cur][0], b[cur][2]);
                    mma_f16(acc[mi][2*p+1], a[mi], b[cur][1], b[cur][3]);
                }
            }
            // ---- l pass ----
            ldm_x4(b[0], stBl + bbase);
#pragma unroll
            for (int p = 0; p < 4; p++) {
                const int cur = p & 1;
                if (p < 3) ldm_x4(b[cur ^ 1], stBl + bbase + (uint32_t)((p + 1) * 1024));
#pragma unroll
                for (int mi = 0; mi < 4; mi++) {
                    mma_f16(acc[mi][2*p],   a[mi], b[cur][0], b[cur][2]);
                    mma_f16(acc[mi][2*p+1], a[mi], b[cur][1], b[cur][3]);
                }
            }
        }
    }

    // ---- epilogue ----
#pragma unroll
    for (int mi = 0; mi < 4; mi++) {
#pragma unroll
        for (int nj = 0; nj < 8; nj++) {
            int colg = n0 + wn * 64 + nj * 8 + q4 * 2;
#pragma unroll
            for (int half = 0; half < 2; half++) {
                int rowg = m0 + wm * 64 + mi * 16 + r8 + half * 8;
                float v0 = acc[mi][nj][half * 2 + 0];
                float v1 = acc[mi][nj][half * 2 + 1];
                if (HASBIAS) { v0 += bias[colg]; v1 += bias[colg + 1]; }
                if (RELU) { v0 = fmaxf(v0, 0.f); v1 = fmaxf(v1, 0.f); }
                if (HALFOUT) {
                    __half2 hp;
                    hp.x = __float2half_rn(v0);
                    hp.y = __float2half_rn(v1);
                    *(__half2*)(Ch + (size_t)rowg * Npad + colg) = hp;
                } else {
                    if (colg < Nreal)     Cf[(size_t)rowg * ldc + colg]     = v0;
                    if (colg + 1 < Nreal) Cf[(size_t)rowg * ldc + colg + 1] = v1;
                }
            }
        }
    }
}

// ---------------- attention: block per (b,h), warp per row ------------------
__global__ __launch_bounds__(256) void attn_kernel() {
    int b = blockIdx.x / Hn;
    int h = blockIdx.x - b * Hn;
    int tid = threadIdx.x;
    int w = tid >> 5, lane = tid & 31;

    __shared__ float4 ks[Tn];
    __shared__ float4 vs[Tn];

    {
        int base = (b * Tn + tid) * 72;
        ks[tid] = *(const float4*)&g_qkv[base + 24 + h * 4];
        vs[tid] = *(const float4*)&g_qkv[base + 48 + h * 4];
    }
    __syncthreads();

    const float scale = 0.05103103630798287f;  // 1/sqrt(384)

    for (int t = w; t < Tn; t += 8) {
        float4 q = *(const float4*)&g_qkv[(b * Tn + t) * 72 + h * 4];
        q.x *= scale; q.y *= scale; q.z *= scale; q.w *= scale;
        float l = 0.f, ax = 0.f, ay = 0.f, az = 0.f, aw = 0.f;
        for (int s = lane; s <= t; s += 32) {
            float4 k = ks[s];
            float p = __expf(q.x*k.x + q.y*k.y + q.z*k.z + q.w*k.w);
            float4 v = vs[s];
            l += p;
            ax = fmaf(p, v.x, ax);
            ay = fmaf(p, v.y, ay);
            az = fmaf(p, v.z, az);
            aw = fmaf(p, v.w, aw);
        }
#pragma unroll
        for (int o = 16; o; o >>= 1) {
            l  += __shfl_xor_sync(0xffffffffu, l,  o);
            ax += __shfl_xor_sync(0xffffffffu, ax, o);
            ay += __shfl_xor_sync(0xffffffffu, ay, o);
            az += __shfl_xor_sync(0xffffffffu, az, o);
            aw += __shfl_xor_sync(0xffffffffu, aw, o);
        }
        if (lane == 0) {
            float inv = 1.f / l;
            size_t rb = (size_t)(b * Tn + t) * 32 + h * 4;
            __half2 p0, p1;
            p0.x = __float2half_rn(ax * inv);
            p0.y = __float2half_rn(ay * inv);
            p1.x = __float2half_rn(az * inv);
            p1.y = __float2half_rn(aw * inv);
            *(__half2*)(g_att + rb)     = p0;
            *(__half2*)(g_att + rb + 2) = p1;
        }
    }

    if (h == 0) {
        size_t rb = (size_t)(b * Tn + tid) * 32;
        __half2 z; z.x = __float2half_rn(0.f); z.y = z.x;
#pragma unroll
        for (int c = 24; c < 32; c += 2)
            *(__half2*)(g_att + rb + c) = z;
    }
}

// ---------------- per-row NLL from logits in out -----------------------------
__global__ __launch_bounds__(256) void rowloss_kernel(const float* __restrict__ out,
                                                      const int* __restrict__ targets) {
    int row = blockIdx.x * 8 + (threadIdx.x >> 5);
    int lane = threadIdx.x & 31;
    const float* lg = out + (size_t)row * Vn;
    float v0 = lg[lane];
    float v1 = lg[lane + 32];
    float v2 = (lane == 0) ? lg[64] : -1e30f;
    float mx = fmaxf(fmaxf(v0, v1), v2);
#pragma unroll
    for (int o = 16; o; o >>= 1) mx = fmaxf(mx, __shfl_xor_sync(0xffffffffu, mx, o));
    float se = __expf(v0 - mx) + __expf(v1 - mx) + ((lane == 0) ? __expf(v2 - mx) : 0.f);
#pragma unroll
    for (int o = 16; o; o >>= 1) se += __shfl_xor_sync(0xffffffffu, se, o);
    if (lane == 0) {
        int tg = targets[row];
        g_rowloss[row] = -(lg[tg] - mx - __logf(se));
    }
}

__global__ __launch_bounds__(256) void loss_reduce_kernel(float* __restrict__ out,
                                                          int out_size) {
    __shared__ float sm[256];
    int tid = threadIdx.x;
    float s = 0.f;
    for (int i = tid; i < BTn; i += 256) s += g_rowloss[i];
    sm[tid] = s;
    __syncthreads();
    for (int st = 128; st > 0; st >>= 1) {
        if (tid < st) sm[tid] += sm[tid + st];
        __syncthreads();
    }
    float loss = sm[0] * (1.f / BTn);
    for (int i = BTn * Vn + tid; i < out_size; i += 256) out[i] = loss;
}

// ---------------------------------------------------------------------------
extern "C" void kernel_launch(void* const* d_in, const int* in_sizes, int n_in,
                              void* d_out, int out_size) {
    const int*   idx     = (const int*)d_in[0];
    const int*   targets = (const int*)d_in[1];
    const float* tok     = (const float*)d_in[2];
    const float* pos     = (const float*)d_in[3];
    const float* Wq      = (const float*)d_in[4];
    const float* Wk      = (const float*)d_in[5];
    const float* Wv      = (const float*)d_in[6];
    const float* Wproj   = (const float*)d_in[7];
    const float* bproj   = (const float*)d_in[8];
    const float* W1      = (const float*)d_in[9];
    const float* b1      = (const float*)d_in[10];
    const float* W2      = (const float*)d_in[11];
    const float* b2      = (const float*)d_in[12];
    const float* Wlm     = (const float*)d_in[13];
    const float* blm     = (const float*)d_in[14];
    float* out = (float*)d_out;

    void *px, *pbqh, *pbql, *pqkv, *pat, *pbph, *pbpl;
    void *px2, *pb1h, *pb1l, *ph, *pb2h, *pb2l, *px3, *pblh, *pbll;
    cudaGetSymbolAddress(&px, g_x);
    cudaGetSymbolAddress(&pbqh, g_bqkvh); cudaGetSymbolAddress(&pbql, g_bqkvl);
    cudaGetSymbolAddress(&pqkv, g_qkv);
    cudaGetSymbolAddress(&pat, g_att);
    cudaGetSymbolAddress(&pbph, g_bprojh); cudaGetSymbolAddress(&pbpl, g_bprojl);
    cudaGetSymbolAddress(&px2, g_x2);
    cudaGetSymbolAddress(&pb1h, g_b1h);   cudaGetSymbolAddress(&pb1l, g_b1l);
    cudaGetSymbolAddress(&ph, g_h);
    cudaGetSymbolAddress(&pb2h, g_b2h);   cudaGetSymbolAddress(&pb2l, g_b2l);
    cudaGetSymbolAddress(&px3, g_x3);
    cudaGetSymbolAddress(&pblh, g_blmh);  cudaGetSymbolAddress(&pbll, g_blml);

    const int SMEM = NSTAGE * STAGE_B;  // 98304
    cudaFuncSetAttribute(tc_gemm<false,false,false>, cudaFuncAttributeMaxDynamicSharedMemorySize, SMEM);
    cudaFuncSetAttribute(tc_gemm<false,true, false>, cudaFuncAttributeMaxDynamicSharedMemorySize, SMEM);
    cudaFuncSetAttribute(tc_gemm<false,true, true >, cudaFuncAttributeMaxDynamicSharedMemorySize, SMEM);
    cudaFuncSetAttribute(tc_gemm<true, true, true >, cudaFuncAttributeMaxDynamicSharedMemorySize, SMEM);

    {
        const int total = PACKT + BTn * Cn;
        pack_embed<<<(total + 255)/256, 256>>>(Wq, Wk, Wv, Wproj, W1, W2, Wlm,
                                               idx, tok, pos);                  // L1
    }

    // qkv: [BT,384] @ [384,72pad128] -> float g_qkv                            // L2
    tc_gemm<false,false,false><<<dim3(1, BTn/128), 128, SMEM>>>(
        (const __half*)px, Cn,
        (const __half*)pbqh, (const __half*)pbql,
        nullptr, (float*)pqkv, 72, 72, nullptr, 0);

    attn_kernel<<<128 * Hn, 256>>>();                                           // L3

    // proj: [BT,32pad] @ [32,384] + bproj -> fp16 x2                           // L4
    tc_gemm<false,true,true><<<dim3(3, BTn/128), 128, SMEM>>>(
        (const __half*)pat, 32,
        (const __half*)pbph, (const __half*)pbpl,
        bproj, nullptr, 0, 0, (__half*)px2, Cn);

    // ffn1: relu([BT,384] @ [384,1536] + b1) -> fp16 h
    tc_gemm<true,true,true><<<dim3(12, BTn/128), 128, SMEM>>>(
        (const __half*)px2, Cn,
        (const __half*)pb1h, (const __half*)pb1l,
        b1, nullptr, 0, 0, (__half*)ph, Fn);

    // ffn2: [BT,1536] @ [1536,384] + b2 -> fp16 x3
    tc_gemm<false,true,true><<<dim3(3, BTn/128), 128, SMEM>>>(
        (const __half*)ph, Fn,
        (const __half*)pb2h, (const __half*)pb2l,
        b2, nullptr, 0, 0, (__half*)px3, Cn);

    // lm: [BT,384] @ [384,65pad128] + blm -> float logits into out
    tc_gemm<false,true,false><<<dim3(1, BTn/128), 128, SMEM>>>(
        (const __half*)px3, Cn,
        (const __half*)pblh, (const __half*)pbll,
        blm, out, Vn, Vn, nullptr, 0);

    rowloss_kernel<<<BTn/8, 256>>>(out, targets);
    loss_reduce_kernel<<<1, 256>>>(out, out_size);
}

// round 10
// speedup vs baseline: 1.0589x; 1.0589x over previous
#include <cuda_runtime.h>
#include <cuda_fp16.h>
#include <cstdint>

#define BTn 32768
#define Tn  256
#define Cn  384
#define Hn  6
#define Vn  65
#define Fn  1536

// ---------------- scratch (device globals; allocation-free rule) -----------
__device__ __half g_x[BTn*Cn];                      // embeddings fp16
__device__ __half g_bqkvh[128*Cn], g_bqkvl[128*Cn]; // qkv W split [Npad=128,K=384]
__device__ float  g_qkv[BTn*72];                    // qkv activations (f32)
__device__ __half g_att[BTn*64];                    // attn out fp16, Kpad=64
__device__ __half g_bprojh[Cn*64], g_bprojl[Cn*64]; // proj W split [384,Kpad=64]
__device__ __half g_x2[BTn*Cn];                     // proj out fp16
__device__ __half g_b1h[Fn*Cn], g_b1l[Fn*Cn];       // W1^T split [1536,384]
__device__ __half g_h[BTn*Fn];                      // ffn hidden fp16
__device__ __half g_b2h[Cn*Fn], g_b2l[Cn*Fn];       // W2^T split [384,1536]
__device__ __half g_x3[BTn*Cn];                     // ffn out fp16
__device__ __half g_blmh[128*Cn], g_blml[128*Cn];   // Wlm^T split [Npad=128,384]
__device__ float  g_rowloss[BTn];

// ---------------- helpers ----------------------------------------------
__device__ __forceinline__ uint32_t smem_u32(const void* p) {
    return (uint32_t)__cvta_generic_to_shared(p);
}

__device__ __forceinline__ void cp16(uint32_t dst, const void* src) {
    asm volatile("cp.async.cg.shared.global [%0], [%1], 16;" :: "r"(dst), "l"(src));
}
#define CP_COMMIT() asm volatile("cp.async.commit_group;" ::: "memory")
#define CP_WAIT(n)  asm volatile("cp.async.wait_group %0;" :: "n"(n) : "memory")

__device__ __forceinline__ void mma_f16(float* d, const uint32_t* a, uint32_t b0, uint32_t b1) {
    asm volatile(
        "mma.sync.aligned.m16n8k16.row.col.f32.f16.f16.f32 "
        "{%0,%1,%2,%3}, {%4,%5,%6,%7}, {%8,%9}, {%0,%1,%2,%3};"
        : "+f"(d[0]), "+f"(d[1]), "+f"(d[2]), "+f"(d[3])
        : "r"(a[0]), "r"(a[1]), "r"(a[2]), "r"(a[3]), "r"(b0), "r"(b1));
}

__device__ __forceinline__ void ldm_x4(uint32_t* r, uint32_t addr) {
    asm volatile("ldmatrix.sync.aligned.m8n8.x4.shared.b16 {%0,%1,%2,%3}, [%4];"
        : "=r"(r[0]), "=r"(r[1]), "=r"(r[2]), "=r"(r[3]) : "r"(addr));
}

__device__ __forceinline__ void split2h(float v, __half& h, __half& l) {
    h = __float2half_rn(v);
    l = __float2half_rn(v - __half2float(h));
}

// ---------------- fused pack + embed (one launch) ---------------------------
#define S0 (128*Cn)
#define S1 (Cn*64)
#define S2 (Fn*Cn)
#define S3 (Cn*Fn)
#define S4 (128*Cn)
#define PACKT (S0 + S1 + S2 + S3 + S4)

__global__ void pack_embed(const float* __restrict__ Wq, const float* __restrict__ Wk,
                           const float* __restrict__ Wv, const float* __restrict__ Wproj,
                           const float* __restrict__ W1, const float* __restrict__ W2,
                           const float* __restrict__ Wlm,
                           const int* __restrict__ idx, const float* __restrict__ tok,
                           const float* __restrict__ pos) {
    int i = blockIdx.x * blockDim.x + threadIdx.x;
    if (i < PACKT) {
        float v; __half *hi, *lo; int o;
        if (i < S0) {
            o = i; int n = o / Cn, k = o - n * Cn;
            if (n < 72) {
                int g = n / 24, rem = n - g * 24, h = rem >> 2, d = rem & 3;
                const float* W = (g == 0) ? Wq : (g == 1) ? Wk : Wv;
                v = W[(h * Cn + k) * 4 + d];
            } else v = 0.f;
            hi = g_bqkvh; lo = g_bqkvl;
        } else if (i < S0 + S1) {
            o = i - S0; int n = o >> 6, k = o & 63;
            v = (k < 24) ? Wproj[k * Cn + n] : 0.f;
            hi = g_bprojh; lo = g_bprojl;
        } else if (i < S0 + S1 + S2) {
            o = i - S0 - S1; int n = o / Cn, k = o - n * Cn;
            v = W1[(size_t)k * Fn + n];
            hi = g_b1h; lo = g_b1l;
        } else if (i < S0 + S1 + S2 + S3) {
            o = i - S0 - S1 - S2; int n = o / Fn, k = o - n * Fn;
            v = W2[(size_t)k * Cn + n];
            hi = g_b2h; lo = g_b2l;
        } else {
            o = i - S0 - S1 - S2 - S3; int n = o / Cn, k = o - n * Cn;
            v = (n < Vn) ? Wlm[k * Vn + n] : 0.f;
            hi = g_blmh; lo = g_blml;
        }
        __half h, l; split2h(v, h, l);
        hi[o] = h; lo[o] = l;
        return;
    }
    int e = i - PACKT;
    if (e >= BTn * Cn) return;
    int bt = e / Cn, c = e - bt * Cn;
    int t = bt & (Tn - 1);
    g_x[e] = __float2half_rn(tok[__ldg(&idx[bt]) * Cn + c] + pos[t * Cn + c]);
}

// ---------------- fp16 2-product GEMM, BK=64, 2-stage double buffer ---------
// C[M,N] = A[M,K] @ (Bh+Bl)^T. 128x128 CTA tile, BK=64, 8 warps (4M x 2N),
// warp tile 32x64. One CP_WAIT + one barrier per 64-K chunk.
// smem tile: [128 rows][64 fp16] = 128B rows, XOR-8 swizzle on 16B chunks.
#define TILE_B 16384
#define STAGE_B (3 * TILE_B)     // A, Bh, Bl = 49152
#define NSTAGE 2

template <bool RELU, bool HASBIAS, bool HALFOUT>
__global__ __launch_bounds__(256, 2) void tc_gemm(
    const __half* __restrict__ A, int Kpad,
    const __half* __restrict__ Bh, const __half* __restrict__ Bl,
    const float* __restrict__ bias,
    float* __restrict__ Cf, int ldc, int Nreal,
    __half* __restrict__ Ch, int Npad)
{
    extern __shared__ char smem[];
    const int tid  = threadIdx.x;
    const int lane = tid & 31, wid = tid >> 5;
    const int wm = wid & 3, wn = wid >> 2;       // 4x2 warp grid, 32x64 tiles
    const int m0 = blockIdx.y * 128, n0 = blockIdx.x * 128;

    const __half* gsrc[3] = {
        A  + (size_t)m0 * Kpad,
        Bh + (size_t)n0 * Kpad,
        Bl + (size_t)n0 * Kpad };

    const int nk = Kpad / 64;
    const uint32_t sbase = smem_u32(smem);

    auto load_stage = [&](int stage, int c) {
        uint32_t dst0 = sbase + stage * STAGE_B;
        int kc0 = c * 64;
#pragma unroll
        for (int tile = 0; tile < 3; tile++) {
            const __half* g = gsrc[tile] + kc0;
#pragma unroll
            for (int t = 0; t < 4; t++) {
                int j = tid + t * 256;               // 0..1023
                int row = j >> 3, sx = j & 7;
                uint32_t sw = (uint32_t)(row * 128 + ((sx ^ (row & 7)) << 4));
                cp16(dst0 + tile * TILE_B + sw, g + (size_t)row * Kpad + sx * 8);
            }
        }
        CP_COMMIT();
    };

    float acc[2][8][4];
#pragma unroll
    for (int mi = 0; mi < 2; mi++)
#pragma unroll
        for (int nj = 0; nj < 8; nj++)
#pragma unroll
            for (int q = 0; q < 4; q++) acc[mi][nj][q] = 0.f;

    load_stage(0, 0);

    // ldmatrix lane addressing (128B rows, XOR-8 swizzle)
    const uint32_t lrow = (uint32_t)(lane & 15);
    const uint32_t lrow128 = lrow * 128;
    const uint32_t xh = (uint32_t)(lane >> 4);
    const uint32_t sxor = lrow & 7;
    const int r8 = lane >> 2, q4 = lane & 3;

    for (int c = 0; c < nk; c++) {
        CP_WAIT(0);
        __syncthreads();
        if (c + 1 < nk) load_stage((c + 1) & 1, c + 1);

        const uint32_t st = sbase + (uint32_t)((c & 1) * STAGE_B);
        const uint32_t stA  = st + (uint32_t)(wm * 4096) + lrow128;
        const uint32_t stBh = st + TILE_B     + (uint32_t)(wn * 8192) + lrow128;
        const uint32_t stBl = st + 2 * TILE_B + (uint32_t)(wn * 8192) + lrow128;

#pragma unroll
        for (int ks = 0; ks < 4; ks++) {
            const uint32_t colx = ((2u * (uint32_t)ks + xh) ^ sxor) << 4;
            uint32_t a0[4], a1[4];
            ldm_x4(a0, stA + colx);
            ldm_x4(a1, stA + colx + 2048);
            uint32_t b[2][4];

            // ---- h pass: 16 independent HMMAs, B n16-frags double-buffered
            ldm_x4(b[0], stBh + colx);
#pragma unroll
            for (int p = 0; p < 4; p++) {
                const int cur = p & 1;
                if (p < 3) ldm_x4(b[cur ^ 1], stBh + colx + (uint32_t)((p + 1) * 2048));
                mma_f16(acc[0][2*p],   a0, b[cur][0], b[cur][2]);
                mma_f16(acc[0][2*p+1], a0, b[cur][1], b[cur][3]);
                mma_f16(acc[1][2*p],   a1, b[cur][0], b[cur][2]);
                mma_f16(acc[1][2*p+1], a1, b[cur][1], b[cur][3]);
            }
            // ---- l pass ----
            ldm_x4(b[0], stBl + colx);
#pragma unroll
            for (int p = 0; p < 4; p++) {
                const int cur = p & 1;
                if (p < 3) ldm_x4(b[cur ^ 1], stBl + colx + (uint32_t)((p + 1) * 2048));
                mma_f16(acc[0][2*p],   a0, b[cur][0], b[cur][2]);
                mma_f16(acc[0][2*p+1], a0, b[cur][1], b[cur][3]);
                mma_f16(acc[1][2*p],   a1, b[cur][0], b[cur][2]);
                mma_f16(acc[1][2*p+1], a1, b[cur][1], b[cur][3]);
            }
        }
    }

    // ---- epilogue ----
#pragma unroll
    for (int mi = 0; mi < 2; mi++) {
#pragma unroll
        for (int nj = 0; nj < 8; nj++) {
            int colg = n0 + wn * 64 + nj * 8 + q4 * 2;
#pragma unroll
            for (int half = 0; half < 2; half++) {
                int rowg = m0 + wm * 32 + mi * 16 + r8 + half * 8;
                float v0 = acc[mi][nj][half * 2 + 0];
                float v1 = acc[mi][nj][half * 2 + 1];
                if (HASBIAS) { v0 += bias[colg]; v1 += bias[colg + 1]; }
                if (RELU) { v0 = fmaxf(v0, 0.f); v1 = fmaxf(v1, 0.f); }
                if (HALFOUT) {
                    __half2 hp;
                    hp.x = __float2half_rn(v0);
                    hp.y = __float2half_rn(v1);
                    *(__half2*)(Ch + (size_t)rowg * Npad + colg) = hp;
                } else {
                    if (colg < Nreal)     Cf[(size_t)rowg * ldc + colg]     = v0;
                    if (colg + 1 < Nreal) Cf[(size_t)rowg * ldc + colg + 1] = v1;
                }
            }
        }
    }
}

// ---------------- attention: block per (b,h), warp per row ------------------
__global__ __launch_bounds__(256) void attn_kernel() {
    int b = blockIdx.x / Hn;
    int h = blockIdx.x - b * Hn;
    int tid = threadIdx.x;
    int w = tid >> 5, lane = tid & 31;

    __shared__ float4 ks[Tn];
    __shared__ float4 vs[Tn];

    {
        int base = (b * Tn + tid) * 72;
        ks[tid] = *(const float4*)&g_qkv[base + 24 + h * 4];
        vs[tid] = *(const float4*)&g_qkv[base + 48 + h * 4];
    }
    __syncthreads();

    const float scale = 0.05103103630798287f;  // 1/sqrt(384)

    for (int t = w; t < Tn; t += 8) {
        float4 q = *(const float4*)&g_qkv[(b * Tn + t) * 72 + h * 4];
        q.x *= scale; q.y *= scale; q.z *= scale; q.w *= scale;
        float l = 0.f, ax = 0.f, ay = 0.f, az = 0.f, aw = 0.f;
        for (int s = lane; s <= t; s += 32) {
            float4 k = ks[s];
            float p = __expf(q.x*k.x + q.y*k.y + q.z*k.z + q.w*k.w);
            float4 v = vs[s];
            l += p;
            ax = fmaf(p, v.x, ax);
            ay = fmaf(p, v.y, ay);
            az = fmaf(p, v.z, az);
            aw = fmaf(p, v.w, aw);
        }
#pragma unroll
        for (int o = 16; o; o >>= 1) {
            l  += __shfl_xor_sync(0xffffffffu, l,  o);
            ax += __shfl_xor_sync(0xffffffffu, ax, o);
            ay += __shfl_xor_sync(0xffffffffu, ay, o);
            az += __shfl_xor_sync(0xffffffffu, az, o);
            aw += __shfl_xor_sync(0xffffffffu, aw, o);
        }
        if (lane == 0) {
            float inv = 1.f / l;
            size_t rb = (size_t)(b * Tn + t) * 64 + h * 4;
            __half2 p0, p1;
            p0.x = __float2half_rn(ax * inv);
            p0.y = __float2half_rn(ay * inv);
            p1.x = __float2half_rn(az * inv);
            p1.y = __float2half_rn(aw * inv);
            *(__half2*)(g_att + rb)     = p0;
            *(__half2*)(g_att + rb + 2) = p1;
        }
    }

    if (h == 0) {
        size_t rb = (size_t)(b * Tn + tid) * 64;
        __half2 z; z.x = __float2half_rn(0.f); z.y = z.x;
#pragma unroll
        for (int c = 24; c < 64; c += 2)
            *(__half2*)(g_att + rb + c) = z;
    }
}

// ---------------- per-row NLL from logits in out -----------------------------
__global__ __launch_bounds__(256) void rowloss_kernel(const float* __restrict__ out,
                                                      const int* __restrict__ targets) {
    int row = blockIdx.x * 8 + (threadIdx.x >> 5);
    int lane = threadIdx.x & 31;
    const float* lg = out + (size_t)row * Vn;
    float v0 = lg[lane];
    float v1 = lg[lane + 32];
    float v2 = (lane == 0) ? lg[64] : -1e30f;
    float mx = fmaxf(fmaxf(v0, v1), v2);
#pragma unroll
    for (int o = 16; o; o >>= 1) mx = fmaxf(mx, __shfl_xor_sync(0xffffffffu, mx, o));
    float se = __expf(v0 - mx) + __expf(v1 - mx) + ((lane == 0) ? __expf(v2 - mx) : 0.f);
#pragma unroll
    for (int o = 16; o; o >>= 1) se += __shfl_xor_sync(0xffffffffu, se, o);
    if (lane == 0) {
        int tg = targets[row];
        g_rowloss[row] = -(lg[tg] - mx - __logf(se));
    }
}

__global__ __launch_bounds__(256) void loss_reduce_kernel(float* __restrict__ out,
                                                          int out_size) {
    __shared__ float sm[256];
    int tid = threadIdx.x;
    float s = 0.f;
    for (int i = tid; i < BTn; i += 256) s += g_rowloss[i];
    sm[tid] = s;
    __syncthreads();
    for (int st = 128; st > 0; st >>= 1) {
        if (tid < st) sm[tid] += sm[tid + st];
        __syncthreads();
    }
    float loss = sm[0] * (1.f / BTn);
    for (int i = BTn * Vn + tid; i < out_size; i += 256) out[i] = loss;
}

// ---------------------------------------------------------------------------
extern "C" void kernel_launch(void* const* d_in, const int* in_sizes, int n_in,
                              void* d_out, int out_size) {
    const int*   idx     = (const int*)d_in[0];
    const int*   targets = (const int*)d_in[1];
    const float* tok     = (const float*)d_in[2];
    const float* pos     = (const float*)d_in[3];
    const float* Wq      = (const float*)d_in[4];
    const float* Wk      = (const float*)d_in[5];
    const float* Wv      = (const float*)d_in[6];
    const float* Wproj   = (const float*)d_in[7];
    const float* bproj   = (const float*)d_in[8];
    const float* W1      = (const float*)d_in[9];
    const float* b1      = (const float*)d_in[10];
    const float* W2      = (const float*)d_in[11];
    const float* b2      = (const float*)d_in[12];
    const float* Wlm     = (const float*)d_in[13];
    const float* blm     = (const float*)d_in[14];
    float* out = (float*)d_out;

    void *px, *pbqh, *pbql, *pqkv, *pat, *pbph, *pbpl;
    void *px2, *pb1h, *pb1l, *ph, *pb2h, *pb2l, *px3, *pblh, *pbll;
    cudaGetSymbolAddress(&px, g_x);
    cudaGetSymbolAddress(&pbqh, g_bqkvh); cudaGetSymbolAddress(&pbql, g_bqkvl);
    cudaGetSymbolAddress(&pqkv, g_qkv);
    cudaGetSymbolAddress(&pat, g_att);
    cudaGetSymbolAddress(&pbph, g_bprojh); cudaGetSymbolAddress(&pbpl, g_bprojl);
    cudaGetSymbolAddress(&px2, g_x2);
    cudaGetSymbolAddress(&pb1h, g_b1h);   cudaGetSymbolAddress(&pb1l, g_b1l);
    cudaGetSymbolAddress(&ph, g_h);
    cudaGetSymbolAddress(&pb2h, g_b2h);   cudaGetSymbolAddress(&pb2l, g_b2l);
    cudaGetSymbolAddress(&px3, g_x3);
    cudaGetSymbolAddress(&pblh, g_blmh);  cudaGetSymbolAddress(&pbll, g_blml);

    const int SMEM = NSTAGE * STAGE_B;  // 98304
    cudaFuncSetAttribute(tc_gemm<false,false,false>, cudaFuncAttributeMaxDynamicSharedMemorySize, SMEM);
    cudaFuncSetAttribute(tc_gemm<false,true, false>, cudaFuncAttributeMaxDynamicSharedMemorySize, SMEM);
    cudaFuncSetAttribute(tc_gemm<false,true, true >, cudaFuncAttributeMaxDynamicSharedMemorySize, SMEM);
    cudaFuncSetAttribute(tc_gemm<true, true, true >, cudaFuncAttributeMaxDynamicSharedMemorySize, SMEM);

    {
        const int total = PACKT + BTn * Cn;
        pack_embed<<<(total + 255)/256, 256>>>(Wq, Wk, Wv, Wproj, W1, W2, Wlm,
                                               idx, tok, pos);                  // L1
    }

    // qkv: [BT,384] @ [384,72pad128] -> float g_qkv                            // L2
    tc_gemm<false,false,false><<<dim3(1, BTn/128), 256, SMEM>>>(
        (const __half*)px, Cn,
        (const __half*)pbqh, (const __half*)pbql,
        nullptr, (float*)pqkv, 72, 72, nullptr, 0);

    attn_kernel<<<128 * Hn, 256>>>();                                           // L3

    // proj: [BT,64pad] @ [64,384] + bproj -> fp16 x2                           // L4
    tc_gemm<false,true,true><<<dim3(3, BTn/128), 256, SMEM>>>(
        (const __half*)pat, 64,
        (const __half*)pbph, (const __half*)pbpl,
        bproj, nullptr, 0, 0, (__half*)px2, Cn);

    // ffn1: relu([BT,384] @ [384,1536] + b1) -> fp16 h
    tc_gemm<true,true,true><<<dim3(12, BTn/128), 256, SMEM>>>(
        (const __half*)px2, Cn,
        (const __half*)pb1h, (const __half*)pb1l,
        b1, nullptr, 0, 0, (__half*)ph, Fn);

    // ffn2: [BT,1536] @ [1536,384] + b2 -> fp16 x3
    tc_gemm<false,true,true><<<dim3(3, BTn/128), 256, SMEM>>>(
        (const __half*)ph, Fn,
        (const __half*)pb2h, (const __half*)pb2l,
        b2, nullptr, 0, 0, (__half*)px3, Cn);

    // lm: [BT,384] @ [384,65pad128] + blm -> float logits into out
    tc_gemm<false,true,false><<<dim3(1, BTn/128), 256, SMEM>>>(
        (const __half*)px3, Cn,
        (const __half*)pblh, (const __half*)pbll,
        blm, out, Vn, Vn, nullptr, 0);

    rowloss_kernel<<<BTn/8, 256>>>(out, targets);
    loss_reduce_kernel<<<1, 256>>>(out, out_size);
}

// round 11
// speedup vs baseline: 1.0593x; 1.0003x over previous
#include <cuda_runtime.h>
#include <cuda_fp16.h>
#include <cstdint>

#define BTn 32768
#define Tn  256
#define Cn  384
#define Hn  6
#define Vn  65
#define Fn  1536

// ---------------- scratch (device globals; allocation-free rule) -----------
__device__ __half g_x[BTn*Cn];                      // embeddings fp16
__device__ __half g_bqkvh[128*Cn], g_bqkvl[128*Cn]; // qkv W split [Npad=128,K=384]
__device__ float  g_qkv[BTn*72];                    // qkv activations (f32)
__device__ __half g_att[BTn*64];                    // attn out fp16, Kpad=64
__device__ __half g_bprojh[Cn*64], g_bprojl[Cn*64]; // proj W split [384,Kpad=64]
__device__ __half g_x2[BTn*Cn];                     // proj out fp16
__device__ __half g_b1h[Fn*Cn], g_b1l[Fn*Cn];       // W1^T split [1536,384]
__device__ __half g_h[BTn*Fn];                      // ffn hidden fp16
__device__ __half g_b2h[Cn*Fn], g_b2l[Cn*Fn];       // W2^T split [384,1536]
__device__ __half g_x3[BTn*Cn];                     // ffn out fp16
__device__ __half g_blmh[128*Cn], g_blml[128*Cn];   // Wlm^T split [Npad=128,384]
__device__ float  g_rowloss[BTn];

// ---------------- helpers ----------------------------------------------
__device__ __forceinline__ uint32_t smem_u32(const void* p) {
    return (uint32_t)__cvta_generic_to_shared(p);
}

__device__ __forceinline__ void cp16(uint32_t dst, const void* src) {
    asm volatile("cp.async.cg.shared.global [%0], [%1], 16;" :: "r"(dst), "l"(src));
}
#define CP_COMMIT() asm volatile("cp.async.commit_group;" ::: "memory")
#define CP_WAIT(n)  asm volatile("cp.async.wait_group %0;" :: "n"(n) : "memory")

__device__ __forceinline__ void mma_f16(float* d, const uint32_t* a, uint32_t b0, uint32_t b1) {
    asm volatile(
        "mma.sync.aligned.m16n8k16.row.col.f32.f16.f16.f32 "
        "{%0,%1,%2,%3}, {%4,%5,%6,%7}, {%8,%9}, {%0,%1,%2,%3};"
        : "+f"(d[0]), "+f"(d[1]), "+f"(d[2]), "+f"(d[3])
        : "r"(a[0]), "r"(a[1]), "r"(a[2]), "r"(a[3]), "r"(b0), "r"(b1));
}

__device__ __forceinline__ void ldm_x4(uint32_t* r, uint32_t addr) {
    asm volatile("ldmatrix.sync.aligned.m8n8.x4.shared.b16 {%0,%1,%2,%3}, [%4];"
        : "=r"(r[0]), "=r"(r[1]), "=r"(r[2]), "=r"(r[3]) : "r"(addr));
}

__device__ __forceinline__ void split2h(float v, __half& h, __half& l) {
    h = __float2half_rn(v);
    l = __float2half_rn(v - __half2float(h));
}

// ---------------- fused pack + embed (one launch) ---------------------------
#define S0 (128*Cn)
#define S1 (Cn*64)
#define S2 (Fn*Cn)
#define S3 (Cn*Fn)
#define S4 (128*Cn)
#define PACKT (S0 + S1 + S2 + S3 + S4)

__global__ void pack_embed(const float* __restrict__ Wq, const float* __restrict__ Wk,
                           const float* __restrict__ Wv, const float* __restrict__ Wproj,
                           const float* __restrict__ W1, const float* __restrict__ W2,
                           const float* __restrict__ Wlm,
                           const int* __restrict__ idx, const float* __restrict__ tok,
                           const float* __restrict__ pos) {
    int i = blockIdx.x * blockDim.x + threadIdx.x;
    if (i < PACKT) {
        float v; __half *hi, *lo; int o;
        if (i < S0) {
            o = i; int n = o / Cn, k = o - n * Cn;
            if (n < 72) {
                int g = n / 24, rem = n - g * 24, h = rem >> 2, d = rem & 3;
                const float* W = (g == 0) ? Wq : (g == 1) ? Wk : Wv;
                v = W[(h * Cn + k) * 4 + d];
            } else v = 0.f;
            hi = g_bqkvh; lo = g_bqkvl;
        } else if (i < S0 + S1) {
            o = i - S0; int n = o >> 6, k = o & 63;
            v = (k < 24) ? Wproj[k * Cn + n] : 0.f;
            hi = g_bprojh; lo = g_bprojl;
        } else if (i < S0 + S1 + S2) {
            o = i - S0 - S1; int n = o / Cn, k = o - n * Cn;
            v = W1[(size_t)k * Fn + n];
            hi = g_b1h; lo = g_b1l;
        } else if (i < S0 + S1 + S2 + S3) {
            o = i - S0 - S1 - S2; int n = o / Fn, k = o - n * Fn;
            v = W2[(size_t)k * Cn + n];
            hi = g_b2h; lo = g_b2l;
        } else {
            o = i - S0 - S1 - S2 - S3; int n = o / Cn, k = o - n * Cn;
            v = (n < Vn) ? Wlm[k * Vn + n] : 0.f;
            hi = g_blmh; lo = g_blml;
        }
        __half h, l; split2h(v, h, l);
        hi[o] = h; lo[o] = l;
        return;
    }
    int e = i - PACKT;
    if (e >= BTn * Cn) return;
    int bt = e / Cn, c = e - bt * Cn;
    int t = bt & (Tn - 1);
    g_x[e] = __float2half_rn(tok[__ldg(&idx[bt]) * Cn + c] + pos[t * Cn + c]);
}

// ---------------- fp16 2-product GEMM, BK=64, seam-free frag pipeline -------
// C[M,N] = A[M,K] @ (Bh+Bl)^T. 128x128 CTA tile, BK=64, 8 warps (4M x 2N),
// warp tile 32x64. One CP_WAIT + one barrier per 64-K chunk.
// smem tile: [128 rows][64 fp16] = 128B rows, XOR-8 swizzle on 16B chunks.
// Fragment schedule: rolling 2-slot B ring prefetches across ALL pass/ks
// boundaries; A double-buffered one ks ahead. Only chunk top is cold.
#define TILE_B 16384
#define STAGE_B (3 * TILE_B)     // A, Bh, Bl = 49152
#define NSTAGE 2

template <bool RELU, bool HASBIAS, bool HALFOUT>
__global__ __launch_bounds__(256, 2) void tc_gemm(
    const __half* __restrict__ A, int Kpad,
    const __half* __restrict__ Bh, const __half* __restrict__ Bl,
    const float* __restrict__ bias,
    float* __restrict__ Cf, int ldc, int Nreal,
    __half* __restrict__ Ch, int Npad)
{
    extern __shared__ char smem[];
    const int tid  = threadIdx.x;
    const int lane = tid & 31, wid = tid >> 5;
    const int wm = wid & 3, wn = wid >> 2;       // 4x2 warp grid, 32x64 tiles
    const int m0 = blockIdx.y * 128, n0 = blockIdx.x * 128;

    const __half* gsrc[3] = {
        A  + (size_t)m0 * Kpad,
        Bh + (size_t)n0 * Kpad,
        Bl + (size_t)n0 * Kpad };

    const int nk = Kpad / 64;
    const uint32_t sbase = smem_u32(smem);

    auto load_stage = [&](int stage, int c) {
        uint32_t dst0 = sbase + stage * STAGE_B;
        int kc0 = c * 64;
#pragma unroll
        for (int tile = 0; tile < 3; tile++) {
            const __half* g = gsrc[tile] + kc0;
#pragma unroll
            for (int t = 0; t < 4; t++) {
                int j = tid + t * 256;               // 0..1023
                int row = j >> 3, sx = j & 7;
                uint32_t sw = (uint32_t)(row * 128 + ((sx ^ (row & 7)) << 4));
                cp16(dst0 + tile * TILE_B + sw, g + (size_t)row * Kpad + sx * 8);
            }
        }
        CP_COMMIT();
    };

    float acc[2][8][4];
#pragma unroll
    for (int mi = 0; mi < 2; mi++)
#pragma unroll
        for (int nj = 0; nj < 8; nj++)
#pragma unroll
            for (int q = 0; q < 4; q++) acc[mi][nj][q] = 0.f;

    load_stage(0, 0);

    // ldmatrix lane addressing (128B rows, XOR-8 swizzle)
    const uint32_t lrow = (uint32_t)(lane & 15);
    const uint32_t lrow128 = lrow * 128;
    const uint32_t xh = (uint32_t)(lane >> 4);
    const uint32_t sxor = lrow & 7;
    const int r8 = lane >> 2, q4 = lane & 3;

    for (int c = 0; c < nk; c++) {
        CP_WAIT(0);
        __syncthreads();
        if (c + 1 < nk) load_stage((c + 1) & 1, c + 1);

        const uint32_t st = sbase + (uint32_t)((c & 1) * STAGE_B);
        const uint32_t stA  = st + (uint32_t)(wm * 4096) + lrow128;
        const uint32_t stBh = st + TILE_B     + (uint32_t)(wn * 8192) + lrow128;
        const uint32_t stBl = st + 2 * TILE_B + (uint32_t)(wn * 8192) + lrow128;

        uint32_t colx[4];
#pragma unroll
        for (int ks = 0; ks < 4; ks++)
            colx[ks] = ((2u * (uint32_t)ks + xh) ^ sxor) << 4;

        // cold start (once per chunk): A(ks0) + first B fragment
        uint32_t a[2][2][4];   // [buf][mfrag][regs]
        uint32_t b[2][4];      // rolling ring
        ldm_x4(a[0][0], stA + colx[0]);
        ldm_x4(a[0][1], stA + colx[0] + 2048);
        ldm_x4(b[0],    stBh + colx[0]);

#pragma unroll
        for (int ks = 0; ks < 4; ks++) {
            const int ca = ks & 1, na = ca ^ 1;
            // ---- h pass ----
#pragma unroll
            for (int p = 0; p < 4; p++) {
                const int cur = (2 * ks * 4 + p) & 1;   // ring parity (8 units*4 even)
                const int nxt = cur ^ 1;
                if (p < 3) ldm_x4(b[nxt], stBh + colx[ks] + (uint32_t)((p + 1) * 2048));
                else       ldm_x4(b[nxt], stBl + colx[ks]);   // l-pass p0
                mma_f16(acc[0][2*p],   a[ca][0], b[cur][0], b[cur][2]);
                mma_f16(acc[0][2*p+1], a[ca][0], b[cur][1], b[cur][3]);
                mma_f16(acc[1][2*p],   a[ca][1], b[cur][0], b[cur][2]);
                mma_f16(acc[1][2*p+1], a[ca][1], b[cur][1], b[cur][3]);
            }
            // ---- l pass ----
#pragma unroll
            for (int p = 0; p < 4; p++) {
                const int cur = ((2 * ks + 1) * 4 + p) & 1;
                const int nxt = cur ^ 1;
                if (p < 3)      ldm_x4(b[nxt], stBl + colx[ks] + (uint32_t)((p + 1) * 2048));
                else if (ks < 3) ldm_x4(b[nxt], stBh + colx[ks + 1]);  // next ks h p0
                if (ks < 3) {
                    if (p == 0) ldm_x4(a[na][0], stA + colx[ks + 1]);
                    if (p == 1) ldm_x4(a[na][1], stA + colx[ks + 1] + 2048);
                }
                mma_f16(acc[0][2*p],   a[ca][0], b[cur][0], b[cur][2]);
                mma_f16(acc[0][2*p+1], a[ca][0], b[cur][1], b[cur][3]);
                mma_f16(acc[1][2*p],   a[ca][1], b[cur][0], b[cur][2]);
                mma_f16(acc[1][2*p+1], a[ca][1], b[cur][1], b[cur][3]);
            }
        }
    }

    // ---- epilogue ----
#pragma unroll
    for (int mi = 0; mi < 2; mi++) {
#pragma unroll
        for (int nj = 0; nj < 8; nj++) {
            int colg = n0 + wn * 64 + nj * 8 + q4 * 2;
#pragma unroll
            for (int half = 0; half < 2; half++) {
                int rowg = m0 + wm * 32 + mi * 16 + r8 + half * 8;
                float v0 = acc[mi][nj][half * 2 + 0];
                float v1 = acc[mi][nj][half * 2 + 1];
                if (HASBIAS) { v0 += bias[colg]; v1 += bias[colg + 1]; }
                if (RELU) { v0 = fmaxf(v0, 0.f); v1 = fmaxf(v1, 0.f); }
                if (HALFOUT) {
                    __half2 hp;
                    hp.x = __float2half_rn(v0);
                    hp.y = __float2half_rn(v1);
                    *(__half2*)(Ch + (size_t)rowg * Npad + colg) = hp;
                } else {
                    if (colg < Nreal)     Cf[(size_t)rowg * ldc + colg]     = v0;
                    if (colg + 1 < Nreal) Cf[(size_t)rowg * ldc + colg + 1] = v1;
                }
            }
        }
    }
}

// ---------------- attention: block per (b,h), warp per row ------------------
__global__ __launch_bounds__(256) void attn_kernel() {
    int b = blockIdx.x / Hn;
    int h = blockIdx.x - b * Hn;
    int tid = threadIdx.x;
    int w = tid >> 5, lane = tid & 31;

    __shared__ float4 ks[Tn];
    __shared__ float4 vs[Tn];

    {
        int base = (b * Tn + tid) * 72;
        ks[tid] = *(const float4*)&g_qkv[base + 24 + h * 4];
        vs[tid] = *(const float4*)&g_qkv[base + 48 + h * 4];
    }
    __syncthreads();

    const float scale = 0.05103103630798287f;  // 1/sqrt(384)

    for (int t = w; t < Tn; t += 8) {
        float4 q = *(const float4*)&g_qkv[(b * Tn + t) * 72 + h * 4];
        q.x *= scale; q.y *= scale; q.z *= scale; q.w *= scale;
        float l = 0.f, ax = 0.f, ay = 0.f, az = 0.f, aw = 0.f;
        for (int s = lane; s <= t; s += 32) {
            float4 k = ks[s];
            float p = __expf(q.x*k.x + q.y*k.y + q.z*k.z + q.w*k.w);
            float4 v = vs[s];
            l += p;
            ax = fmaf(p, v.x, ax);
            ay = fmaf(p, v.y, ay);
            az = fmaf(p, v.z, az);
            aw = fmaf(p, v.w, aw);
        }
#pragma unroll
        for (int o = 16; o; o >>= 1) {
            l  += __shfl_xor_sync(0xffffffffu, l,  o);
            ax += __shfl_xor_sync(0xffffffffu, ax, o);
            ay += __shfl_xor_sync(0xffffffffu, ay, o);
            az += __shfl_xor_sync(0xffffffffu, az, o);
            aw += __shfl_xor_sync(0xffffffffu, aw, o);
        }
        if (lane == 0) {
            float inv = 1.f / l;
            size_t rb = (size_t)(b * Tn + t) * 64 + h * 4;
            __half2 p0, p1;
            p0.x = __float2half_rn(ax * inv);
            p0.y = __float2half_rn(ay * inv);
            p1.x = __float2half_rn(az * inv);
            p1.y = __float2half_rn(aw * inv);
            *(__half2*)(g_att + rb)     = p0;
            *(__half2*)(g_att + rb + 2) = p1;
        }
    }

    if (h == 0) {
        size_t rb = (size_t)(b * Tn + tid) * 64;
        __half2 z; z.x = __float2half_rn(0.f); z.y = z.x;
#pragma unroll
        for (int c = 24; c < 64; c += 2)
            *(__half2*)(g_att + rb + c) = z;
    }
}

// ---------------- per-row NLL from logits in out -----------------------------
__global__ __launch_bounds__(256) void rowloss_kernel(const float* __restrict__ out,
                                                      const int* __restrict__ targets) {
    int row = blockIdx.x * 8 + (threadIdx.x >> 5);
    int lane = threadIdx.x & 31;
    const float* lg = out + (size_t)row * Vn;
    float v0 = lg[lane];
    float v1 = lg[lane + 32];
    float v2 = (lane == 0) ? lg[64] : -1e30f;
    float mx = fmaxf(fmaxf(v0, v1), v2);
#pragma unroll
    for (int o = 16; o; o >>= 1) mx = fmaxf(mx, __shfl_xor_sync(0xffffffffu, mx, o));
    float se = __expf(v0 - mx) + __expf(v1 - mx) + ((lane == 0) ? __expf(v2 - mx) : 0.f);
#pragma unroll
    for (int o = 16; o; o >>= 1) se += __shfl_xor_sync(0xffffffffu, se, o);
    if (lane == 0) {
        int tg = targets[row];
        g_rowloss[row] = -(lg[tg] - mx - __logf(se));
    }
}

__global__ __launch_bounds__(256) void loss_reduce_kernel(float* __restrict__ out,
                                                          int out_size) {
    __shared__ float sm[256];
    int tid = threadIdx.x;
    float s = 0.f;
    for (int i = tid; i < BTn; i += 256) s += g_rowloss[i];
    sm[tid] = s;
    __syncthreads();
    for (int st = 128; st > 0; st >>= 1) {
        if (tid < st) sm[tid] += sm[tid + st];
        __syncthreads();
    }
    float loss = sm[0] * (1.f / BTn);
    for (int i = BTn * Vn + tid; i < out_size; i += 256) out[i] = loss;
}

// ---------------------------------------------------------------------------
extern "C" void kernel_launch(void* const* d_in, const int* in_sizes, int n_in,
                              void* d_out, int out_size) {
    const int*   idx     = (const int*)d_in[0];
    const int*   targets = (const int*)d_in[1];
    const float* tok     = (const float*)d_in[2];
    const float* pos     = (const float*)d_in[3];
    const float* Wq      = (const float*)d_in[4];
    const float* Wk      = (const float*)d_in[5];
    const float* Wv      = (const float*)d_in[6];
    const float* Wproj   = (const float*)d_in[7];
    const float* bproj   = (const float*)d_in[8];
    const float* W1      = (const float*)d_in[9];
    const float* b1      = (const float*)d_in[10];
    const float* W2      = (const float*)d_in[11];
    const float* b2      = (const float*)d_in[12];
    const float* Wlm     = (const float*)d_in[13];
    const float* blm     = (const float*)d_in[14];
    float* out = (float*)d_out;

    void *px, *pbqh, *pbql, *pqkv, *pat, *pbph, *pbpl;
    void *px2, *pb1h, *pb1l, *ph, *pb2h, *pb2l, *px3, *pblh, *pbll;
    cudaGetSymbolAddress(&px, g_x);
    cudaGetSymbolAddress(&pbqh, g_bqkvh); cudaGetSymbolAddress(&pbql, g_bqkvl);
    cudaGetSymbolAddress(&pqkv, g_qkv);
    cudaGetSymbolAddress(&pat, g_att);
    cudaGetSymbolAddress(&pbph, g_bprojh); cudaGetSymbolAddress(&pbpl, g_bprojl);
    cudaGetSymbolAddress(&px2, g_x2);
    cudaGetSymbolAddress(&pb1h, g_b1h);   cudaGetSymbolAddress(&pb1l, g_b1l);
    cudaGetSymbolAddress(&ph, g_h);
    cudaGetSymbolAddress(&pb2h, g_b2h);   cudaGetSymbolAddress(&pb2l, g_b2l);
    cudaGetSymbolAddress(&px3, g_x3);
    cudaGetSymbolAddress(&pblh, g_blmh);  cudaGetSymbolAddress(&pbll, g_blml);

    const int SMEM = NSTAGE * STAGE_B;  // 98304
    cudaFuncSetAttribute(tc_gemm<false,false,false>, cudaFuncAttributeMaxDynamicSharedMemorySize, SMEM);
    cudaFuncSetAttribute(tc_gemm<false,true, false>, cudaFuncAttributeMaxDynamicSharedMemorySize, SMEM);
    cudaFuncSetAttribute(tc_gemm<false,true, true >, cudaFuncAttributeMaxDynamicSharedMemorySize, SMEM);
    cudaFuncSetAttribute(tc_gemm<true, true, true >, cudaFuncAttributeMaxDynamicSharedMemorySize, SMEM);

    {
        const int total = PACKT + BTn * Cn;
        pack_embed<<<(total + 255)/256, 256>>>(Wq, Wk, Wv, Wproj, W1, W2, Wlm,
                                               idx, tok, pos);                  // L1
    }

    // qkv: [BT,384] @ [384,72pad128] -> float g_qkv                            // L2
    tc_gemm<false,false,false><<<dim3(1, BTn/128), 256, SMEM>>>(
        (const __half*)px, Cn,
        (const __half*)pbqh, (const __half*)pbql,
        nullptr, (float*)pqkv, 72, 72, nullptr, 0);

    attn_kernel<<<128 * Hn, 256>>>();                                           // L3

    // proj: [BT,64pad] @ [64,384] + bproj -> fp16 x2                           // L4
    tc_gemm<false,true,true><<<dim3(3, BTn/128), 256, SMEM>>>(
        (const __half*)pat, 64,
        (const __half*)pbph, (const __half*)pbpl,
        bproj, nullptr, 0, 0, (__half*)px2, Cn);

    // ffn1: relu([BT,384] @ [384,1536] + b1) -> fp16 h
    tc_gemm<true,true,true><<<dim3(12, BTn/128), 256, SMEM>>>(
        (const __half*)px2, Cn,
        (const __half*)pb1h, (const __half*)pb1l,
        b1, nullptr, 0, 0, (__half*)ph, Fn);

    // ffn2: [BT,1536] @ [1536,384] + b2 -> fp16 x3
    tc_gemm<false,true,true><<<dim3(3, BTn/128), 256, SMEM>>>(
        (const __half*)ph, Fn,
        (const __half*)pb2h, (const __half*)pb2l,
        b2, nullptr, 0, 0, (__half*)px3, Cn);

    // lm: [BT,384] @ [384,65pad128] + blm -> float logits into out
    tc_gemm<false,true,false><<<dim3(1, BTn/128), 256, SMEM>>>(
        (const __half*)px3, Cn,
        (const __half*)pblh, (const __half*)pbll,
        blm, out, Vn, Vn, nullptr, 0);

    rowloss_kernel<<<BTn/8, 256>>>(out, targets);
    loss_reduce_kernel<<<1, 256>>>(out, out_size);
}